// round 2
// baseline (speedup 1.0000x reference)
#include <cuda_runtime.h>
#include <cstdint>

// MeanAggregator: out[b, :] = (1/K) * sum_k features[neigh_idx[b,k], :]
// features: [U=1e6, D=128] fp32, neigh_idx: [B=1e5, K=10] INT32 (JAX downcasts
// int64 -> int32 without x64 mode), out: [B, 128] fp32.
//
// One warp per output row. Lane l owns float4 chunk l (32 * 16B = 512B = one
// full feature row), so every gathered row is one fully coalesced 512B access.
// Indices loaded by lanes 0..K-1 and broadcast with shfl; K fully unrolled so
// the 10 independent LDG.128s are front-batched (MLP ~ 10).

#define D 128
#define KNEIGH 10

__global__ __launch_bounds__(256) void mean_agg_kernel(
    const float* __restrict__ features,
    const int* __restrict__ neigh_idx,
    float* __restrict__ out,
    int B)
{
    const int warp_global = (blockIdx.x * blockDim.x + threadIdx.x) >> 5;
    const int lane = threadIdx.x & 31;
    if (warp_global >= B) return;

    // Lanes 0..9 each load one neighbor index for this row.
    int my_idx = 0;
    if (lane < KNEIGH) {
        my_idx = neigh_idx[(long long)warp_global * KNEIGH + lane];
    }

    float4 acc = make_float4(0.f, 0.f, 0.f, 0.f);

    #pragma unroll
    for (int k = 0; k < KNEIGH; ++k) {
        long long j = __shfl_sync(0xffffffffu, my_idx, k);
        const float4* row = reinterpret_cast<const float4*>(features + j * D);
        float4 v = row[lane];
        acc.x += v.x;
        acc.y += v.y;
        acc.z += v.z;
        acc.w += v.w;
    }

    const float inv_k = 1.0f / (float)KNEIGH;
    float4 r = make_float4(acc.x * inv_k, acc.y * inv_k, acc.z * inv_k, acc.w * inv_k);
    reinterpret_cast<float4*>(out + (long long)warp_global * D)[lane] = r;
}

extern "C" void kernel_launch(void* const* d_in, const int* in_sizes, int n_in,
                              void* d_out, int out_size)
{
    const float* features = (const float*)d_in[0];
    const int* neigh_idx  = (const int*)d_in[1];
    float* out            = (float*)d_out;

    const int B = in_sizes[1] / KNEIGH;   // 100,000

    const int warps_per_block = 256 / 32; // 8
    const int grid = (B + warps_per_block - 1) / warps_per_block; // 12,500

    mean_agg_kernel<<<grid, 256>>>(features, neigh_idx, out, B);
}